// round 1
// baseline (speedup 1.0000x reference)
#include <cuda_runtime.h>

// ---------------------------------------------------------------------------
// QuantumClassifier: analytic factorization of the 8q circuit into a per-sample
// 4q circuit (16 complex amps, register-resident) + constant K-side factors.
// ---------------------------------------------------------------------------

struct Cx { float r, i; };

__device__ __align__(16) float g_gates[2][80];  // [Q|V]: 8 stages x (Rot 4x Cx = 8 floats) + 8 x (crx c,s)
__device__ float g_xk[4];                       // <X_w> of the constant K state

// generic 1-qubit gate on wire W of a 4-qubit state (stride 8>>W)
template<int W>
__device__ __forceinline__ void ap1g(Cx* p, Cx u0, Cx u1, Cx u2, Cx u3) {
    constexpr int s = 8 >> W;
    #pragma unroll
    for (int i = 0; i < 16; ++i) if (!(i & s)) {
        Cx a = p[i], b = p[i + s];
        p[i]   = Cx{ u0.r*a.r - u0.i*a.i + u1.r*b.r - u1.i*b.i,
                     u0.r*a.i + u0.i*a.r + u1.r*b.i + u1.i*b.r };
        p[i+s] = Cx{ u2.r*a.r - u2.i*a.i + u3.r*b.r - u3.i*b.i,
                     u2.r*a.i + u2.i*a.r + u3.r*b.i + u3.i*b.r };
    }
}

// RX butterfly (u00=c, u01=u10=-i s, u11=c)
template<int W>
__device__ __forceinline__ void rxg(Cx* p, float c, float s) {
    constexpr int st = 8 >> W;
    #pragma unroll
    for (int i = 0; i < 16; ++i) if (!(i & st)) {
        Cx a = p[i], b = p[i + st];
        p[i]    = Cx{ c*a.r + s*b.i, c*a.i - s*b.r };
        p[i+st] = Cx{ c*b.r + s*a.i, c*b.i - s*a.r };
    }
}

// controlled-RX: control wire A (bit set), target wire B
template<int A, int B>
__device__ __forceinline__ void crxg(Cx* p, float c, float s) {
    constexpr int sa = 8 >> A, sb = 8 >> B;
    #pragma unroll
    for (int i = 0; i < 16; ++i) if ((i & sa) && !(i & sb)) {
        Cx a = p[i], b = p[i + sb];
        p[i]    = Cx{ c*a.r + s*b.i, c*a.i - s*b.r };
        p[i+sb] = Cx{ c*b.r + s*a.i, c*b.i - s*a.r };
    }
}

template<int A, int B>
__device__ __forceinline__ void cnotg(Cx* p) {
    constexpr int sa = 8 >> A, sb = 8 >> B;
    #pragma unroll
    for (int i = 0; i < 16; ++i) if ((i & sa) && !(i & sb)) {
        Cx t = p[i]; p[i] = p[i + sb]; p[i + sb] = t;
    }
}

// RZ(t): bit0 *= (c - i s), bit1 *= (c + i s), with (c,s)=cos/sin(t/2)
template<int W>
__device__ __forceinline__ void rzg(Cx* p, float c, float s) {
    constexpr int st = 8 >> W;
    #pragma unroll
    for (int i = 0; i < 16; ++i) {
        Cx a = p[i];
        float ss = (i & st) ? s : -s;
        p[i] = Cx{ c*a.r - ss*a.i, c*a.i + ss*a.r };
    }
}

template<int W>
__device__ __forceinline__ float expZ(const Cx* p) {
    constexpr int st = 8 >> W;
    float v = 0.f;
    #pragma unroll
    for (int i = 0; i < 16; ++i) {
        float m = p[i].r*p[i].r + p[i].i*p[i].i;
        v += (i & st) ? -m : m;
    }
    return v;
}

template<int W>
__device__ __forceinline__ float expX(const Cx* p) {
    constexpr int st = 8 >> W;
    float v = 0.f;
    #pragma unroll
    for (int i = 0; i < 16; ++i) if (!(i & st))
        v += p[i].r*p[i+st].r + p[i].i*p[i+st].i;
    return 2.f * v;
}

template<int A, int B>
__device__ __forceinline__ void stage(Cx* p, const float* g, int i) {
    Cx u0{g[8*i+0], g[8*i+1]}, u1{g[8*i+2], g[8*i+3]},
       u2{g[8*i+4], g[8*i+5]}, u3{g[8*i+6], g[8*i+7]};
    ap1g<A>(p, u0, u1, u2, u3);
    crxg<A, B>(p, g[64+2*i], g[64+2*i+1]);
    cnotg<A, B>(p);
}

// initQKV wire-pair order: (0,1)(1,2)(2,3)(3,0)(0,3)(1,0)(2,1)(3,2)
__device__ __forceinline__ void init_qkv(Cx* p, const float* g) {
    stage<0,1>(p, g, 0); stage<1,2>(p, g, 1); stage<2,3>(p, g, 2); stage<3,0>(p, g, 3);
    stage<0,3>(p, g, 4); stage<1,0>(p, g, 5); stage<2,1>(p, g, 6); stage<3,2>(p, g, 7);
}

__device__ void fill_gates(const float* rot, const float* crx, float* g) {
    for (int i = 0; i < 8; ++i) {
        float phi = rot[3*i], th = rot[3*i+1], om = rot[3*i+2];
        float sa, ca, sb, cb, st2, ct2;
        sincosf(0.5f*(phi+om), &sa, &ca);
        sincosf(0.5f*(phi-om), &sb, &cb);
        sincosf(0.5f*th, &st2, &ct2);
        g[8*i+0] =  ca*ct2; g[8*i+1] = -sa*ct2;   // u00 = e^{-iA} cos
        g[8*i+2] = -cb*st2; g[8*i+3] = -sb*st2;   // u01 = -e^{+iB} sin
        g[8*i+4] =  cb*st2; g[8*i+5] = -sb*st2;   // u10 = e^{-iB} sin
        g[8*i+6] =  ca*ct2; g[8*i+7] =  sa*ct2;   // u11 = e^{+iA} cos
        float cc, sc;
        sincosf(0.5f*crx[i], &sc, &cc);
        g[64+2*i] = cc; g[64+2*i+1] = sc;
    }
}

__global__ void setup_kernel(const float* q_rot, const float* k_rot, const float* v_rot,
                             const float* q_crx, const float* k_crx, const float* v_crx) {
    if (threadIdx.x != 0 || blockIdx.x != 0) return;
    fill_gates(q_rot, q_crx, g_gates[0]);
    fill_gates(v_rot, v_crx, g_gates[1]);
    float kg[80];
    fill_gates(k_rot, k_crx, kg);
    Cx p[16];
    #pragma unroll
    for (int i = 0; i < 16; ++i) p[i] = Cx{0.f, 0.f};
    p[0] = Cx{1.f, 0.f};
    init_qkv(p, kg);
    g_xk[0] = expX<0>(p); g_xk[1] = expX<1>(p);
    g_xk[2] = expX<2>(p); g_xk[3] = expX<3>(p);
}

#define ROWS 64
#define PI_F 3.14159265358979f

__global__ void __launch_bounds__(ROWS)
qc_main(const float* __restrict__ x1,
        const float* __restrict__ pre_w, const float* __restrict__ pre_b,
        const float* __restrict__ ln_w, const float* __restrict__ ln_b,
        const float* __restrict__ head_w, const float* __restrict__ head_b,
        float* __restrict__ out, int B)
{
    __shared__ float sh[ROWS][97];   // 97 pad -> conflict-free row reads
    __shared__ float wsh[4*96];
    int base = blockIdx.x * ROWS;
    int rows = min(ROWS, B - base);
    for (int e = threadIdx.x; e < rows * 96; e += ROWS)
        sh[e / 96][e % 96] = x1[base * 96 + e];
    for (int e = threadIdx.x; e < 384; e += ROWS)
        wsh[e] = pre_w[e];
    __syncthreads();
    if ((int)threadIdx.x >= rows) return;

    // ---- pre-linear: x[4] = x1_row @ pre_w.T + pre_b ----
    float a0 = pre_b[0], a1 = pre_b[1], a2 = pre_b[2], a3 = pre_b[3];
    #pragma unroll
    for (int j = 0; j < 96; ++j) {
        float v = sh[threadIdx.x][j];
        a0 += v * wsh[j];       a1 += v * wsh[96 + j];
        a2 += v * wsh[192 + j]; a3 += v * wsh[288 + j];
    }
    float xw[4] = {a0, a1, a2, a3};
    float ec[4], es[4];
    #pragma unroll
    for (int w = 0; w < 4; ++w) sincosf(0.5f * xw[w], &es[w], &ec[w]);

    // ---- product-state after RX embed on |0000>: amp[i] = prod(bit? -i*s : c) ----
    Cx pinit[16];
    #pragma unroll
    for (int i = 0; i < 16; ++i) {
        float m = ((i & 8) ? es[0] : ec[0]) * ((i & 4) ? es[1] : ec[1])
                * ((i & 2) ? es[2] : ec[2]) * ((i & 1) ? es[3] : ec[3]);
        int k = __popc(i) & 3;   // (-i)^k
        pinit[i] = (k == 0) ? Cx{m, 0.f} : (k == 1) ? Cx{0.f, -m}
                 : (k == 2) ? Cx{-m, 0.f} : Cx{0.f, m};
    }

    // ---- Q circuit: embed, initQKV(Q), embed again ----
    Cx p[16];
    #pragma unroll
    for (int i = 0; i < 16; ++i) p[i] = pinit[i];
    init_qkv(p, g_gates[0]);
    rxg<0>(p, ec[0], es[0]); rxg<1>(p, ec[1], es[1]);
    rxg<2>(p, ec[2], es[2]); rxg<3>(p, ec[3], es[3]);

    float score[4];
    {
        float z0 = expZ<0>(p), z1 = expZ<1>(p), z2 = expZ<2>(p), z3 = expZ<3>(p);
        float q0 = expX<0>(p), q1 = expX<1>(p), q2 = expX<2>(p), q3 = expX<3>(p);
        float m0 = q0 * g_xk[0], m1 = q1 * g_xk[1], m2 = q2 * g_xk[2], m3 = q3 * g_xk[3];
        score[0] = sqrtf(z0*z0 + m0*m0);
        score[1] = sqrtf(z1*z1 + m1*m1);
        score[2] = sqrtf(z2*z2 + m2*m2);
        score[3] = sqrtf(z3*z3 + m3*m3);
    }

    // ---- V circuit: embed, initQKV(V), RZ(tanh(score)*pi), CNOT chain ----
    #pragma unroll
    for (int i = 0; i < 16; ++i) p[i] = pinit[i];
    init_qkv(p, g_gates[1]);
    #pragma unroll
    for (int w = 0; w < 4; ++w) {
        float h = tanhf(score[w]) * (0.5f * PI_F);   // t/2
        float c, s;
        sincosf(h, &s, &c);
        if (w == 0) rzg<0>(p, c, s);
        else if (w == 1) rzg<1>(p, c, s);
        else if (w == 2) rzg<2>(p, c, s);
        else rzg<3>(p, c, s);
    }
    cnotg<0,1>(p); cnotg<1,2>(p); cnotg<2,3>(p);

    float o[8];
    o[0] = expZ<0>(p); o[1] = expZ<1>(p); o[2] = expZ<2>(p); o[3] = expZ<3>(p);
    o[4] = expX<0>(p); o[5] = expX<1>(p); o[6] = expX<2>(p); o[7] = expX<3>(p);

    // ---- LayerNorm(8) + exact GELU + head ----
    float mu = 0.f;
    #pragma unroll
    for (int k = 0; k < 8; ++k) mu += o[k];
    mu *= 0.125f;
    float var = 0.f;
    #pragma unroll
    for (int k = 0; k < 8; ++k) { float d = o[k] - mu; var += d * d; }
    var *= 0.125f;
    float inv = rsqrtf(var + 1e-5f);

    float r0 = head_b[0], r1 = head_b[1];
    #pragma unroll
    for (int k = 0; k < 8; ++k) {
        float y = (o[k] - mu) * inv * ln_w[k] + ln_b[k];
        float g = 0.5f * y * (1.f + erff(y * 0.70710678118654752f));
        r0 += g * head_w[k];
        r1 += g * head_w[8 + k];
    }
    int row = base + threadIdx.x;
    *reinterpret_cast<float2*>(out + 2 * row) = make_float2(r0, r1);
}

extern "C" void kernel_launch(void* const* d_in, const int* in_sizes, int n_in,
                              void* d_out, int out_size) {
    const float* x1     = (const float*)d_in[0];
    const float* pre_w  = (const float*)d_in[1];
    const float* pre_b  = (const float*)d_in[2];
    const float* q_rot  = (const float*)d_in[3];
    const float* k_rot  = (const float*)d_in[4];
    const float* v_rot  = (const float*)d_in[5];
    const float* q_crx  = (const float*)d_in[6];
    const float* k_crx  = (const float*)d_in[7];
    const float* v_crx  = (const float*)d_in[8];
    const float* ln_w   = (const float*)d_in[9];
    const float* ln_b   = (const float*)d_in[10];
    const float* head_w = (const float*)d_in[11];
    const float* head_b = (const float*)d_in[12];
    int B = in_sizes[0] / 96;

    setup_kernel<<<1, 32>>>(q_rot, k_rot, v_rot, q_crx, k_crx, v_crx);
    qc_main<<<(B + ROWS - 1) / ROWS, ROWS>>>(x1, pre_w, pre_b, ln_w, ln_b,
                                             head_w, head_b, (float*)d_out, B);
}

// round 2
// speedup vs baseline: 1.6243x; 1.6243x over previous
#include <cuda_runtime.h>

// ---------------------------------------------------------------------------
// QuantumClassifier, fused single kernel.
// Analytic factorization: 8q circuit -> per-sample 4q Q-circuit (register
// resident, 16 complex amps) x constant K-side <X> factors. Q and V circuits
// interleaved for 2x ILP (kernel is latency-bound at ~0.9 warps/SMSP).
// Gate tables + constant-K expectation computed per block in shared memory
// (removes the separate setup kernel + graph-node serialization).
// ---------------------------------------------------------------------------

struct Cx { float r, i; };

#define PI_F 3.14159265358979f
#define ROWS 64

// generic 1-qubit gate on wire W of a 4-qubit state (stride 8>>W)
template<int W>
__device__ __forceinline__ void ap1g(Cx* p, Cx u0, Cx u1, Cx u2, Cx u3) {
    constexpr int s = 8 >> W;
    #pragma unroll
    for (int i = 0; i < 16; ++i) if (!(i & s)) {
        Cx a = p[i], b = p[i + s];
        p[i]   = Cx{ u0.r*a.r - u0.i*a.i + u1.r*b.r - u1.i*b.i,
                     u0.r*a.i + u0.i*a.r + u1.r*b.i + u1.i*b.r };
        p[i+s] = Cx{ u2.r*a.r - u2.i*a.i + u3.r*b.r - u3.i*b.i,
                     u2.r*a.i + u2.i*a.r + u3.r*b.i + u3.i*b.r };
    }
}

// RX butterfly (u00=c, u01=u10=-i s, u11=c)
template<int W>
__device__ __forceinline__ void rxg(Cx* p, float c, float s) {
    constexpr int st = 8 >> W;
    #pragma unroll
    for (int i = 0; i < 16; ++i) if (!(i & st)) {
        Cx a = p[i], b = p[i + st];
        p[i]    = Cx{ c*a.r + s*b.i, c*a.i - s*b.r };
        p[i+st] = Cx{ c*b.r + s*a.i, c*b.i - s*a.r };
    }
}

// controlled-RX: control wire A (bit set), target wire B
template<int A, int B>
__device__ __forceinline__ void crxg(Cx* p, float c, float s) {
    constexpr int sa = 8 >> A, sb = 8 >> B;
    #pragma unroll
    for (int i = 0; i < 16; ++i) if ((i & sa) && !(i & sb)) {
        Cx a = p[i], b = p[i + sb];
        p[i]    = Cx{ c*a.r + s*b.i, c*a.i - s*b.r };
        p[i+sb] = Cx{ c*b.r + s*a.i, c*b.i - s*a.r };
    }
}

template<int A, int B>
__device__ __forceinline__ void cnotg(Cx* p) {
    constexpr int sa = 8 >> A, sb = 8 >> B;
    #pragma unroll
    for (int i = 0; i < 16; ++i) if ((i & sa) && !(i & sb)) {
        Cx t = p[i]; p[i] = p[i + sb]; p[i + sb] = t;
    }
}

// RZ(t): bit0 *= (c - i s), bit1 *= (c + i s), with (c,s)=cos/sin(t/2)
template<int W>
__device__ __forceinline__ void rzg(Cx* p, float c, float s) {
    constexpr int st = 8 >> W;
    #pragma unroll
    for (int i = 0; i < 16; ++i) {
        Cx a = p[i];
        float ss = (i & st) ? s : -s;
        p[i] = Cx{ c*a.r - ss*a.i, c*a.i + ss*a.r };
    }
}

// all 4 <Z_w> and <X_w>; magnitudes computed once
__device__ __forceinline__ void measZX(const Cx* p, float* z, float* x) {
    float mag[16];
    #pragma unroll
    for (int i = 0; i < 16; ++i) mag[i] = p[i].r*p[i].r + p[i].i*p[i].i;
    #pragma unroll
    for (int w = 0; w < 4; ++w) {
        const int st = 8 >> w;
        float zz = 0.f, xx = 0.f;
        #pragma unroll
        for (int i = 0; i < 16; ++i) zz += (i & st) ? -mag[i] : mag[i];
        #pragma unroll
        for (int i = 0; i < 16; ++i) if (!(i & st))
            xx += p[i].r*p[i+st].r + p[i].i*p[i+st].i;
        z[w] = zz; x[w] = 2.f * xx;
    }
}

template<int A, int B>
__device__ __forceinline__ void stage(Cx* p, const float* g, int i) {
    Cx u0{g[8*i+0], g[8*i+1]}, u1{g[8*i+2], g[8*i+3]},
       u2{g[8*i+4], g[8*i+5]}, u3{g[8*i+6], g[8*i+7]};
    ap1g<A>(p, u0, u1, u2, u3);
    crxg<A, B>(p, g[64+2*i], g[64+2*i+1]);
    cnotg<A, B>(p);
}

// wire-pair order: (0,1)(1,2)(2,3)(3,0)(0,3)(1,0)(2,1)(3,2)
__device__ __forceinline__ void init_qkv(Cx* p, const float* g) {
    stage<0,1>(p, g, 0); stage<1,2>(p, g, 1); stage<2,3>(p, g, 2); stage<3,0>(p, g, 3);
    stage<0,3>(p, g, 4); stage<1,0>(p, g, 5); stage<2,1>(p, g, 6); stage<3,2>(p, g, 7);
}

// Q and V circuits interleaved stage-by-stage: two independent dependency chains
template<int A, int B>
__device__ __forceinline__ void stage2(Cx* pq, Cx* pv, const float* gq, const float* gv, int i) {
    stage<A, B>(pq, gq, i);
    stage<A, B>(pv, gv, i);
}

__device__ __forceinline__ void init_qkv2(Cx* pq, Cx* pv, const float* gq, const float* gv) {
    stage2<0,1>(pq, pv, gq, gv, 0); stage2<1,2>(pq, pv, gq, gv, 1);
    stage2<2,3>(pq, pv, gq, gv, 2); stage2<3,0>(pq, pv, gq, gv, 3);
    stage2<0,3>(pq, pv, gq, gv, 4); stage2<1,0>(pq, pv, gq, gv, 5);
    stage2<2,1>(pq, pv, gq, gv, 6); stage2<3,2>(pq, pv, gq, gv, 7);
}

__global__ void __launch_bounds__(ROWS)
qc_fused(const float* __restrict__ x1,
         const float* __restrict__ pre_w, const float* __restrict__ pre_b,
         const float* __restrict__ q_rot, const float* __restrict__ k_rot,
         const float* __restrict__ v_rot,
         const float* __restrict__ q_crx, const float* __restrict__ k_crx,
         const float* __restrict__ v_crx,
         const float* __restrict__ ln_w, const float* __restrict__ ln_b,
         const float* __restrict__ head_w, const float* __restrict__ head_b,
         float* __restrict__ out, int B)
{
    __shared__ __align__(16) float sg[3][80];       // Q, K, V gate tables
    __shared__ float sxk[4];                        // <X_w> of constant K state
    __shared__ __align__(16) float wsh[384];        // pre_w
    __shared__ __align__(16) float tile[ROWS][100]; // x1 tile, stride 100 -> LDS.128 conflict-free

    const int t = threadIdx.x;
    const int base = blockIdx.x * ROWS;
    const int rows = min(ROWS, B - base);

    // ---- stage x1 tile through smem with coalesced float4 loads ----
    const float4* x4 = reinterpret_cast<const float4*>(x1 + (size_t)base * 96);
    for (int f = t; f < rows * 24; f += ROWS) {
        float4 v = x4[f];
        int r = f / 24, c = f % 24;
        *reinterpret_cast<float4*>(&tile[r][4 * c]) = v;
    }
    for (int e = t; e < 384; e += ROWS) wsh[e] = pre_w[e];

    // ---- gate tables: 24 threads, one (circuit, stage) each ----
    if (t < 24) {
        int c = t >> 3, s = t & 7;
        const float* rot = (c == 0) ? q_rot : (c == 1) ? k_rot : v_rot;
        const float* crx = (c == 0) ? q_crx : (c == 1) ? k_crx : v_crx;
        float phi = rot[3*s], th = rot[3*s+1], om = rot[3*s+2];
        float sa, ca, sb, cb, st2, ct2;
        sincosf(0.5f*(phi+om), &sa, &ca);
        sincosf(0.5f*(phi-om), &sb, &cb);
        sincosf(0.5f*th, &st2, &ct2);
        float* g = sg[c];
        g[8*s+0] =  ca*ct2; g[8*s+1] = -sa*ct2;   // u00 = e^{-iA} cos
        g[8*s+2] = -cb*st2; g[8*s+3] = -sb*st2;   // u01 = -e^{+iB} sin
        g[8*s+4] =  cb*st2; g[8*s+5] = -sb*st2;   // u10 = e^{-iB} sin
        g[8*s+6] =  ca*ct2; g[8*s+7] =  sa*ct2;   // u11 = e^{+iA} cos
        float cc, sc; sincosf(0.5f*crx[s], &sc, &cc);
        g[64+2*s] = cc; g[64+2*s+1] = sc;
    }
    __syncthreads();

    // ---- constant K state -> <X_w> factors (one thread per block) ----
    if (t == 0) {
        Cx p[16];
        #pragma unroll
        for (int i = 0; i < 16; ++i) p[i] = Cx{0.f, 0.f};
        p[0] = Cx{1.f, 0.f};
        init_qkv(p, sg[1]);
        float z[4], xk[4];
        measZX(p, z, xk);
        sxk[0] = xk[0]; sxk[1] = xk[1]; sxk[2] = xk[2]; sxk[3] = xk[3];
    }
    __syncthreads();
    if (t >= rows) return;

    // ---- pre-linear: 16 partial accumulators (chain 96 -> 24 FMA) ----
    float ax[4] = {0,0,0,0}, ay[4] = {0,0,0,0}, az[4] = {0,0,0,0}, aw[4] = {0,0,0,0};
    #pragma unroll
    for (int k = 0; k < 24; ++k) {
        float4 v = *reinterpret_cast<const float4*>(&tile[t][4 * k]);
        #pragma unroll
        for (int o = 0; o < 4; ++o) {
            float4 w = *reinterpret_cast<const float4*>(&wsh[96 * o + 4 * k]);
            ax[o] += v.x * w.x; ay[o] += v.y * w.y;
            az[o] += v.z * w.z; aw[o] += v.w * w.w;
        }
    }
    float ec[4], es[4];
    #pragma unroll
    for (int o = 0; o < 4; ++o) {
        float xv = ((ax[o] + ay[o]) + (az[o] + aw[o])) + pre_b[o];
        __sincosf(0.5f * xv, &es[o], &ec[o]);
    }

    // ---- product state after RX embed: amp[i] = (-i)^popc * prod(c/s) ----
    Cx pq[16], pv[16];
    #pragma unroll
    for (int i = 0; i < 16; ++i) {
        float m = ((i & 8) ? es[0] : ec[0]) * ((i & 4) ? es[1] : ec[1])
                * ((i & 2) ? es[2] : ec[2]) * ((i & 1) ? es[3] : ec[3]);
        int k = __popc(i) & 3;
        Cx v = (k == 0) ? Cx{m, 0.f} : (k == 1) ? Cx{0.f, -m}
             : (k == 2) ? Cx{-m, 0.f} : Cx{0.f, m};
        pq[i] = v; pv[i] = v;
    }

    // ---- Q and V initQKV interleaved (independent chains) ----
    init_qkv2(pq, pv, sg[0], sg[2]);

    // ---- Q: second embed, measure, score ----
    rxg<0>(pq, ec[0], es[0]); rxg<1>(pq, ec[1], es[1]);
    rxg<2>(pq, ec[2], es[2]); rxg<3>(pq, ec[3], es[3]);

    float zq[4], xq[4];
    measZX(pq, zq, xq);

    float sc_c[4], sc_s[4];
    #pragma unroll
    for (int w = 0; w < 4; ++w) {
        float m  = xq[w] * sxk[w];
        float sc = sqrtf(zq[w]*zq[w] + m*m);
        float e  = __expf(2.f * sc);                 // tanh via exp (sc >= 0)
        float th = __fdividef(e - 1.f, e + 1.f);
        __sincosf(th * (0.5f * PI_F), &sc_s[w], &sc_c[w]);  // RZ half-angle
    }

    // ---- V tail: RZ, CNOT chain, measure ----
    rzg<0>(pv, sc_c[0], sc_s[0]); rzg<1>(pv, sc_c[1], sc_s[1]);
    rzg<2>(pv, sc_c[2], sc_s[2]); rzg<3>(pv, sc_c[3], sc_s[3]);
    cnotg<0,1>(pv); cnotg<1,2>(pv); cnotg<2,3>(pv);

    float o[8];
    {
        float z[4], x[4];
        measZX(pv, z, x);
        o[0]=z[0]; o[1]=z[1]; o[2]=z[2]; o[3]=z[3];
        o[4]=x[0]; o[5]=x[1]; o[6]=x[2]; o[7]=x[3];
    }

    // ---- LayerNorm(8) + exact GELU + head ----
    float mu = 0.f;
    #pragma unroll
    for (int k = 0; k < 8; ++k) mu += o[k];
    mu *= 0.125f;
    float var = 0.f;
    #pragma unroll
    for (int k = 0; k < 8; ++k) { float d = o[k] - mu; var += d * d; }
    var *= 0.125f;
    float inv = rsqrtf(var + 1e-5f);

    float r0 = head_b[0], r1 = head_b[1];
    #pragma unroll
    for (int k = 0; k < 8; ++k) {
        float y = (o[k] - mu) * inv * ln_w[k] + ln_b[k];
        float g = 0.5f * y * (1.f + erff(y * 0.70710678118654752f));
        r0 += g * head_w[k];
        r1 += g * head_w[8 + k];
    }
    int row = base + t;
    *reinterpret_cast<float2*>(out + 2 * row) = make_float2(r0, r1);
}

extern "C" void kernel_launch(void* const* d_in, const int* in_sizes, int n_in,
                              void* d_out, int out_size) {
    const float* x1     = (const float*)d_in[0];
    const float* pre_w  = (const float*)d_in[1];
    const float* pre_b  = (const float*)d_in[2];
    const float* q_rot  = (const float*)d_in[3];
    const float* k_rot  = (const float*)d_in[4];
    const float* v_rot  = (const float*)d_in[5];
    const float* q_crx  = (const float*)d_in[6];
    const float* k_crx  = (const float*)d_in[7];
    const float* v_crx  = (const float*)d_in[8];
    const float* ln_w   = (const float*)d_in[9];
    const float* ln_b   = (const float*)d_in[10];
    const float* head_w = (const float*)d_in[11];
    const float* head_b = (const float*)d_in[12];
    int B = in_sizes[0] / 96;

    qc_fused<<<(B + ROWS - 1) / ROWS, ROWS>>>(x1, pre_w, pre_b,
                                              q_rot, k_rot, v_rot,
                                              q_crx, k_crx, v_crx,
                                              ln_w, ln_b, head_w, head_b,
                                              (float*)d_out, B);
}

// round 5
// speedup vs baseline: 2.1400x; 1.3175x over previous
#include <cuda_runtime.h>

// ---------------------------------------------------------------------------
// QuantumClassifier: 2 lanes per sample, fully convergent.
// Even lane simulates the Q circuit, odd lane the V circuit — identical
// instruction stream, data-selected gate tables/coefficients (no divergence).
// Score crosses Q->V via SHFL. Doubles warp count (latency-bound kernel) and
// shortens the per-lane dependency chain ~40%.
// ---------------------------------------------------------------------------

struct Cx { float r, i; };

#define PI_F  3.14159265358979f
#define SROWS 64      // samples per block
#define TPB   128     // 2 threads per sample

// generic 1-qubit gate on wire W of a 4-qubit state (stride 8>>W)
template<int W>
__device__ __forceinline__ void ap1g(Cx* p, Cx u0, Cx u1, Cx u2, Cx u3) {
    constexpr int s = 8 >> W;
    #pragma unroll
    for (int i = 0; i < 16; ++i) if (!(i & s)) {
        Cx a = p[i], b = p[i + s];
        p[i]   = Cx{ u0.r*a.r - u0.i*a.i + u1.r*b.r - u1.i*b.i,
                     u0.r*a.i + u0.i*a.r + u1.r*b.i + u1.i*b.r };
        p[i+s] = Cx{ u2.r*a.r - u2.i*a.i + u3.r*b.r - u3.i*b.i,
                     u2.r*a.i + u2.i*a.r + u3.r*b.i + u3.i*b.r };
    }
}

// RX butterfly (u00=c, u01=u10=-i s, u11=c)
template<int W>
__device__ __forceinline__ void rxg(Cx* p, float c, float s) {
    constexpr int st = 8 >> W;
    #pragma unroll
    for (int i = 0; i < 16; ++i) if (!(i & st)) {
        Cx a = p[i], b = p[i + st];
        p[i]    = Cx{ c*a.r + s*b.i, c*a.i - s*b.r };
        p[i+st] = Cx{ c*b.r + s*a.i, c*b.i - s*a.r };
    }
}

// controlled-RX: control wire A, target wire B
template<int A, int B>
__device__ __forceinline__ void crxg(Cx* p, float c, float s) {
    constexpr int sa = 8 >> A, sb = 8 >> B;
    #pragma unroll
    for (int i = 0; i < 16; ++i) if ((i & sa) && !(i & sb)) {
        Cx a = p[i], b = p[i + sb];
        p[i]    = Cx{ c*a.r + s*b.i, c*a.i - s*b.r };
        p[i+sb] = Cx{ c*b.r + s*a.i, c*b.i - s*a.r };
    }
}

template<int A, int B>
__device__ __forceinline__ void cnotg(Cx* p) {
    constexpr int sa = 8 >> A, sb = 8 >> B;
    #pragma unroll
    for (int i = 0; i < 16; ++i) if ((i & sa) && !(i & sb)) {
        Cx t = p[i]; p[i] = p[i + sb]; p[i + sb] = t;
    }
}

// RZ(t): bit0 *= (c - i s), bit1 *= (c + i s)
template<int W>
__device__ __forceinline__ void rzg(Cx* p, float c, float s) {
    constexpr int st = 8 >> W;
    #pragma unroll
    for (int i = 0; i < 16; ++i) {
        Cx a = p[i];
        float ss = (i & st) ? s : -s;
        p[i] = Cx{ c*a.r - ss*a.i, c*a.i + ss*a.r };
    }
}

// all 4 <Z_w> and <X_w>, magnitudes computed once
__device__ __forceinline__ void measZX(const Cx* p, float* z, float* x) {
    float mag[16];
    #pragma unroll
    for (int i = 0; i < 16; ++i) mag[i] = p[i].r*p[i].r + p[i].i*p[i].i;
    #pragma unroll
    for (int w = 0; w < 4; ++w) {
        const int st = 8 >> w;
        float zz = 0.f, xx = 0.f;
        #pragma unroll
        for (int i = 0; i < 16; ++i) zz += (i & st) ? -mag[i] : mag[i];
        #pragma unroll
        for (int i = 0; i < 16; ++i) if (!(i & st))
            xx += p[i].r*p[i+st].r + p[i].i*p[i+st].i;
        z[w] = zz; x[w] = 2.f * xx;
    }
}

template<int A, int B>
__device__ __forceinline__ void stage(Cx* p, const float* g, int i) {
    Cx u0{g[8*i+0], g[8*i+1]}, u1{g[8*i+2], g[8*i+3]},
       u2{g[8*i+4], g[8*i+5]}, u3{g[8*i+6], g[8*i+7]};
    ap1g<A>(p, u0, u1, u2, u3);
    crxg<A, B>(p, g[64+2*i], g[64+2*i+1]);
    cnotg<A, B>(p);
}

// wire-pair order: (0,1)(1,2)(2,3)(3,0)(0,3)(1,0)(2,1)(3,2)
__device__ __forceinline__ void init_qkv(Cx* p, const float* g) {
    stage<0,1>(p, g, 0); stage<1,2>(p, g, 1); stage<2,3>(p, g, 2); stage<3,0>(p, g, 3);
    stage<0,3>(p, g, 4); stage<1,0>(p, g, 5); stage<2,1>(p, g, 6); stage<3,2>(p, g, 7);
}

// one Rot+CRX stage of a gate table
__device__ __forceinline__ void build_stage(const float* rot, const float* crx,
                                            int s, float* g) {
    float phi = rot[3*s], th = rot[3*s+1], om = rot[3*s+2];
    float sa, ca, sb, cb, st2, ct2;
    sincosf(0.5f*(phi+om), &sa, &ca);
    sincosf(0.5f*(phi-om), &sb, &cb);
    sincosf(0.5f*th, &st2, &ct2);
    g[8*s+0] =  ca*ct2; g[8*s+1] = -sa*ct2;   // u00 = e^{-iA} cos
    g[8*s+2] = -cb*st2; g[8*s+3] = -sb*st2;   // u01 = -e^{+iB} sin
    g[8*s+4] =  cb*st2; g[8*s+5] = -sb*st2;   // u10 = e^{-iB} sin
    g[8*s+6] =  ca*ct2; g[8*s+7] =  sa*ct2;   // u11 = e^{+iA} cos
    float cc, sc; sincosf(0.5f*crx[s], &sc, &cc);
    g[64+2*s] = cc; g[64+2*s+1] = sc;
}

__global__ void __launch_bounds__(TPB)
qc_pair(const float* __restrict__ x1,
        const float* __restrict__ pre_w, const float* __restrict__ pre_b,
        const float* __restrict__ q_rot, const float* __restrict__ k_rot,
        const float* __restrict__ v_rot,
        const float* __restrict__ q_crx, const float* __restrict__ k_crx,
        const float* __restrict__ v_crx,
        const float* __restrict__ ln_w, const float* __restrict__ ln_b,
        const float* __restrict__ head_w, const float* __restrict__ head_b,
        float* __restrict__ out, int B)
{
    __shared__ __align__(16) float sg[3][80];        // Q / K / V gate tables
    __shared__ float sxk[4];                         // <X_w> of constant K state
    __shared__ __align__(16) float wsh[384];         // pre_w
    __shared__ __align__(16) float tile[SROWS][100]; // x1 tile (pad 100)

    const int t = threadIdx.x;
    const int base = blockIdx.x * SROWS;
    const int rows = min(SROWS, B - base);

    if (t >= 96) {
        // warp 3: K table -> K simulation -> sxk  (overlaps warps 0-2)
        if (t < 104) build_stage(k_rot, k_crx, t - 96, sg[1]);
        __syncwarp();
        if (t == 96) {
            Cx p[16];
            #pragma unroll
            for (int i = 0; i < 16; ++i) p[i] = Cx{0.f, 0.f};
            p[0] = Cx{1.f, 0.f};
            init_qkv(p, sg[1]);
            float z[4], xk[4];
            measZX(p, z, xk);
            sxk[0] = xk[0]; sxk[1] = xk[1]; sxk[2] = xk[2]; sxk[3] = xk[3];
        }
    } else {
        if (t < 16) {
            int c = t >> 3, s = t & 7;            // c=0 -> Q, c=1 -> V
            build_stage(c ? v_rot : q_rot, c ? v_crx : q_crx, s, sg[c ? 2 : 0]);
        }
        // stage x1 tile (coalesced float4) + pre_w, threads 0..95
        const float4* x4 = reinterpret_cast<const float4*>(x1 + (size_t)base * 96);
        for (int f = t; f < rows * 24; f += 96) {
            float4 v = x4[f];
            int r = f / 24, c = f % 24;
            *reinterpret_cast<float4*>(&tile[r][4 * c]) = v;
        }
        for (int e = t; e < 384; e += 96) wsh[e] = pre_w[e];
    }
    __syncthreads();

    const int sid   = t >> 1;                 // sample within block
    const int sidc  = min(sid, rows - 1);     // clamp (keeps warp convergent)
    const bool isQ  = !(t & 1);

    // ---- pre-linear, split 48/48 across the lane pair ----
    const int k0 = (t & 1) * 12;              // float4 offset for this lane
    float ax[4] = {0,0,0,0}, ay[4] = {0,0,0,0}, az[4] = {0,0,0,0}, aw[4] = {0,0,0,0};
    #pragma unroll
    for (int k = 0; k < 12; ++k) {
        float4 v = *reinterpret_cast<const float4*>(&tile[sidc][4 * (k0 + k)]);
        #pragma unroll
        for (int o = 0; o < 4; ++o) {
            float4 w = *reinterpret_cast<const float4*>(&wsh[96 * o + 4 * (k0 + k)]);
            ax[o] += v.x * w.x; ay[o] += v.y * w.y;
            az[o] += v.z * w.z; aw[o] += v.w * w.w;
        }
    }
    float ec[4], es[4];
    #pragma unroll
    for (int o = 0; o < 4; ++o) {
        float part = (ax[o] + ay[o]) + (az[o] + aw[o]);
        float xv = part + __shfl_xor_sync(0xffffffffu, part, 1) + pre_b[o];
        __sincosf(0.5f * xv, &es[o], &ec[o]);
    }

    // ---- product state after RX embed: amp[i] = (-i)^popc * prod(c/s) ----
    Cx p[16];
    #pragma unroll
    for (int i = 0; i < 16; ++i) {
        float m = ((i & 8) ? es[0] : ec[0]) * ((i & 4) ? es[1] : ec[1])
                * ((i & 2) ? es[2] : ec[2]) * ((i & 1) ? es[3] : ec[3]);
        int k = __popc(i) & 3;
        p[i] = (k == 0) ? Cx{m, 0.f} : (k == 1) ? Cx{0.f, -m}
             : (k == 2) ? Cx{-m, 0.f} : Cx{0.f, m};
    }

    // ---- role circuit: even lane -> Q table, odd lane -> V table ----
    init_qkv(p, isQ ? sg[0] : sg[2]);

    // second RX embed: Q uses real angles, V uses identity (c=1,s=0)
    {
        float c0 = isQ ? ec[0] : 1.f, s0 = isQ ? es[0] : 0.f;
        float c1 = isQ ? ec[1] : 1.f, s1 = isQ ? es[1] : 0.f;
        float c2 = isQ ? ec[2] : 1.f, s2 = isQ ? es[2] : 0.f;
        float c3 = isQ ? ec[3] : 1.f, s3 = isQ ? es[3] : 0.f;
        rxg<0>(p, c0, s0); rxg<1>(p, c1, s1); rxg<2>(p, c2, s2); rxg<3>(p, c3, s3);
    }

    // measurement (valid for Q lanes; V lanes compute don't-care in lockstep)
    float zq[4], xq[4];
    measZX(p, zq, xq);

    // score -> RZ half-angle cos/sin (all lanes execute; only Q-lane values used)
    float scc[4], scs[4];
    #pragma unroll
    for (int w = 0; w < 4; ++w) {
        float m  = xq[w] * sxk[w];
        float sc = sqrtf(zq[w]*zq[w] + m*m);
        float e  = __expf(2.f * sc);                  // tanh(sc), sc >= 0
        float th = __fdividef(e - 1.f, e + 1.f);
        __sincosf(th * (0.5f * PI_F), &scs[w], &scc[w]);
    }
    // broadcast the Q-lane's values to both lanes of the pair
    const int src = (t & 31) & ~1;
    #pragma unroll
    for (int w = 0; w < 4; ++w) {
        scc[w] = __shfl_sync(0xffffffffu, scc[w], src);
        scs[w] = __shfl_sync(0xffffffffu, scs[w], src);
    }

    // ---- V tail (Q lanes compute don't-care in lockstep) ----
    rzg<0>(p, scc[0], scs[0]); rzg<1>(p, scc[1], scs[1]);
    rzg<2>(p, scc[2], scs[2]); rzg<3>(p, scc[3], scs[3]);
    cnotg<0,1>(p); cnotg<1,2>(p); cnotg<2,3>(p);

    float o[8];
    {
        float z[4], x[4];
        measZX(p, z, x);
        o[0]=z[0]; o[1]=z[1]; o[2]=z[2]; o[3]=z[3];
        o[4]=x[0]; o[5]=x[1]; o[6]=x[2]; o[7]=x[3];
    }

    // ---- LayerNorm(8) + exact GELU + head ----
    float mu = 0.f;
    #pragma unroll
    for (int k = 0; k < 8; ++k) mu += o[k];
    mu *= 0.125f;
    float var = 0.f;
    #pragma unroll
    for (int k = 0; k < 8; ++k) { float d = o[k] - mu; var += d * d; }
    var *= 0.125f;
    float inv = rsqrtf(var + 1e-5f);

    float r0 = head_b[0], r1 = head_b[1];
    #pragma unroll
    for (int k = 0; k < 8; ++k) {
        float y = (o[k] - mu) * inv * ln_w[k] + ln_b[k];
        float g = 0.5f * y * (1.f + erff(y * 0.70710678118654752f));
        r0 += g * head_w[k];
        r1 += g * head_w[8 + k];
    }

    if ((t & 1) && sid < rows)   // odd (V) lane holds the valid result
        *reinterpret_cast<float2*>(out + 2 * (base + sid)) = make_float2(r0, r1);
}

extern "C" void kernel_launch(void* const* d_in, const int* in_sizes, int n_in,
                              void* d_out, int out_size) {
    const float* x1     = (const float*)d_in[0];
    const float* pre_w  = (const float*)d_in[1];
    const float* pre_b  = (const float*)d_in[2];
    const float* q_rot  = (const float*)d_in[3];
    const float* k_rot  = (const float*)d_in[4];
    const float* v_rot  = (const float*)d_in[5];
    const float* q_crx  = (const float*)d_in[6];
    const float* k_crx  = (const float*)d_in[7];
    const float* v_crx  = (const float*)d_in[8];
    const float* ln_w   = (const float*)d_in[9];
    const float* ln_b   = (const float*)d_in[10];
    const float* head_w = (const float*)d_in[11];
    const float* head_b = (const float*)d_in[12];
    int B = in_sizes[0] / 96;

    qc_pair<<<(B + SROWS - 1) / SROWS, TPB>>>(x1, pre_w, pre_b,
                                              q_rot, k_rot, v_rot,
                                              q_crx, k_crx, v_crx,
                                              ln_w, ln_b, head_w, head_b,
                                              (float*)d_out, B);
}